// round 15
// baseline (speedup 1.0000x reference)
#include <cuda_runtime.h>
#include <cuda_fp16.h>
#include <cstdint>

// ---------------------------------------------------------------------------
// LMMD loss — HMMA fp16 single-term Gram mainloop + fused epilogue.
//   bw closed form: sum(l2) = 2n*sum(||x||^2) - 2*||sum x||^2  (fp32/double)
//   K(l2) = z + z^2 + z^4 + z^8 + z^16, z = exp(-l2/(16*bw))
//   loss = (1/n_idx) * sum_pq (u_p.u_q) K_pq, u = +s_vec / -t_vec rows.
//   Upper-triangular 128x128 tiles only (x2 off-diagonal).
//   g ~= fp16(x) . fp16(y)  (fp32 accum; sq-norms exact fp32 so only the
//   cross term carries fp16 rounding; est. loss rel err ~2e-4 < 1e-3)
// R15: resubmit of R14 (infra failure, kernel never ran).
//      Legacy HMMA measured at ~25cyc/m16n8k16 (pipe floor) -> cut MACs 3x
//      by replacing the bf16 3-term split with fp16 hi-only. 4-stage pipe.
// ---------------------------------------------------------------------------

#define B_ROWS 4096
#define D_DIM  256
#define NCLS   31
#define NTOT   8192
#define BM     128
#define KC     32              // K per chunk = 64B fp16 rows
#define NCHUNK 8
#define NSTAGE 4
#define NT     64
#define NPAIR  2080
#define NSRCT  32              // tiles 0..31 hold source rows

#define TILE_BYTES  8192       // 128 rows x 64 B
#define STAGE_BYTES 16384      // 2 tiles (Ah, Bh)

// ---- device scratch ----
__device__ __align__(16) __half d_Xh[NTOT * D_DIM];
__device__ __align__(16) float d_W[NTOT * 32];
__device__ int   d_labS[B_ROWS];
__device__ float d_sq[NTOT];
__device__ float d_colsum[D_DIM];
__device__ float d_scnt[NCLS];
__device__ float d_tcnt[NCLS];
__device__ float d_targc[NCLS];
__device__ float d_sscale[NCLS];
__device__ float d_tscale[NCLS];
__device__ float d_cz;
__device__ float d_inv_nidx;
__device__ float d_partial[NPAIR];
__device__ int   d_lab64;

// ---- helpers ----
__device__ __forceinline__ uint32_t smem_u32(const void* p) {
    uint32_t a;
    asm("{ .reg .u64 t; cvta.to.shared.u64 t, %1; cvt.u32.u64 %0, t; }" : "=r"(a) : "l"(p));
    return a;
}
#define CP_ASYNC16(dst, src) \
    asm volatile("cp.async.cg.shared.global [%0], [%1], 16;" :: "r"(dst), "l"(src))
#define CP_COMMIT() asm volatile("cp.async.commit_group;" ::: "memory")
#define CP_WAIT(n)  asm volatile("cp.async.wait_group %0;" :: "n"(n) : "memory")

#define LDSM4(r, a) \
    asm volatile("ldmatrix.sync.aligned.m8n8.x4.shared.b16 {%0,%1,%2,%3}, [%4];" \
        : "=r"((r)[0]), "=r"((r)[1]), "=r"((r)[2]), "=r"((r)[3]) : "r"(a))

__device__ __forceinline__ void mma_f16(float* c, const uint32_t* a, const uint32_t* b) {
    asm volatile(
        "mma.sync.aligned.m16n8k16.row.col.f32.f16.f16.f32 "
        "{%0,%1,%2,%3}, {%4,%5,%6,%7}, {%8,%9}, {%0,%1,%2,%3};"
        : "+f"(c[0]), "+f"(c[1]), "+f"(c[2]), "+f"(c[3])
        : "r"(a[0]), "r"(a[1]), "r"(a[2]), "r"(a[3]), "r"(b[0]), "r"(b[1]));
}

__device__ __forceinline__ const float* row_ptr(const float* s, const float* t, int p) {
    return (p < B_ROWS) ? (s + (size_t)p * D_DIM) : (t + (size_t)(p - B_ROWS) * D_DIM);
}
__device__ __forceinline__ int get_label(const void* sl, int i) {
    if (d_lab64) return (int)((const long long*)sl)[i];
    return ((const int*)sl)[i];
}

// ---------------------------------------------------------------------------
// small kernels
// ---------------------------------------------------------------------------
__global__ void k_detect(const void* sl) {
    __shared__ int any;
    if (threadIdx.x == 0) any = 0;
    __syncthreads();
    const int* a = (const int*)sl;
    int local = 0;
    for (int i = threadIdx.x; i < 2048; i += blockDim.x)
        if (a[2 * i + 1] != 0) local = 1;
    if (local) atomicOr(&any, 1);
    __syncthreads();
    if (threadIdx.x == 0) d_lab64 = any ? 0 : 1;
}

__global__ void k_zero() {
    int t = threadIdx.x;
    if (t < NCLS) { d_scnt[t] = 0.f; d_tcnt[t] = 0.f; d_targc[t] = 0.f; }
    if (t < D_DIM) d_colsum[t] = 0.f;
}

__global__ void k_stats(const void* sl, const float* __restrict__ tl) {
    __shared__ float ssh[NCLS], tsh[NCLS], ash[NCLS];
    int tid = threadIdx.x;
    if (tid < NCLS) { ssh[tid] = 0.f; tsh[tid] = 0.f; ash[tid] = 0.f; }
    __syncthreads();
    int i = blockIdx.x * 256 + tid;
    int lab = get_label(sl, i);
    atomicAdd(&ssh[lab], 1.f);
    const float* row = tl + (size_t)i * NCLS;
    float best = row[0];
    int arg = 0;
    atomicAdd(&tsh[0], best);
    #pragma unroll
    for (int c = 1; c < NCLS; c++) {
        float v = row[c];
        atomicAdd(&tsh[c], v);
        if (v > best) { best = v; arg = c; }
    }
    atomicAdd(&ash[arg], 1.f);
    __syncthreads();
    if (tid < NCLS) {
        atomicAdd(&d_scnt[tid],  ssh[tid]);
        atomicAdd(&d_tcnt[tid],  tsh[tid]);
        atomicAdd(&d_targc[tid], ash[tid]);
    }
}

// fused: column sums + row sq-norms + fp16 conversion.  grid 1024 x 256
__global__ void k_prep(const float* __restrict__ src, const float* __restrict__ tgt) {
    __shared__ float cs[256];
    int tid = threadIdx.x;
    cs[tid] = 0.f;
    __syncthreads();
    int w = tid >> 5, lane = tid & 31;
    int row = blockIdx.x * 8 + w;
    const float* p = row_ptr(src, tgt, row) + lane * 8;
    float4 v0 = *(const float4*)p;
    float4 v1 = *(const float4*)(p + 4);
    float xs[8] = {v0.x, v0.y, v0.z, v0.w, v1.x, v1.y, v1.z, v1.w};

    float s = 0.f;
    #pragma unroll
    for (int e = 0; e < 8; e++) s = fmaf(xs[e], xs[e], s);
    #pragma unroll
    for (int off = 16; off > 0; off >>= 1) s += __shfl_xor_sync(0xffffffffu, s, off);
    if (lane == 0) d_sq[row] = s;

    int cb = lane * 8;
    #pragma unroll
    for (int e = 0; e < 8; e++) atomicAdd(&cs[cb + e], xs[e]);

    uint32_t ph[4];
    #pragma unroll
    for (int e = 0; e < 4; e++) {
        __half h0 = __float2half_rn(xs[2 * e]);
        __half h1 = __float2half_rn(xs[2 * e + 1]);
        ph[e] = (uint32_t)__half_as_ushort(h0) | ((uint32_t)__half_as_ushort(h1) << 16);
    }
    size_t o = (size_t)row * D_DIM + lane * 8;
    *(uint4*)(d_Xh + o) = make_uint4(ph[0], ph[1], ph[2], ph[3]);

    __syncthreads();
    atomicAdd(&d_colsum[tid], cs[tid]);
}

__global__ void k_finalize() {
    __shared__ double dred[256];
    int tid = threadIdx.x;
    if (tid == 0) {
        float nidx = 0.f;
        for (int c = 0; c < NCLS; c++) {
            float m = (d_scnt[c] > 0.f && d_targc[c] > 0.f) ? 1.f : 0.f;
            nidx += m;
            float sden = (d_scnt[c] == 0.f) ? 100.f : d_scnt[c];
            float tden = (d_tcnt[c] == 0.f) ? 100.f : d_tcnt[c];
            d_sscale[c] = m / sden;
            d_tscale[c] = m / tden;
        }
        if (nidx < 1.f) nidx = 1.f;
        d_inv_nidx = 1.f / nidx;
    }
    double s = 0.0;
    for (int i = tid; i < NTOT; i += 256)
        s += (double)d_sq[i] * (2.0 * (double)NTOT);
    for (int i = tid; i < D_DIM; i += 256) {
        double v = (double)d_colsum[i];
        s -= 2.0 * v * v;
    }
    dred[tid] = s;
    __syncthreads();
    for (int st = 128; st > 0; st >>= 1) {
        if (tid < st) dred[tid] += dred[tid + st];
        __syncthreads();
    }
    if (tid == 0) {
        float bw = (float)(dred[0] / (8192.0 * 8192.0 - 8192.0));
        bw = fmaxf(bw, 1e-6f) * 0.25f;
        d_cz = -1.4426950408889634f / (bw * 16.f);
    }
}

__global__ void k_weights(const void* sl, const float* __restrict__ tl) {
    int p = blockIdx.x * 256 + threadIdx.x;
    float* w = d_W + (size_t)p * 32;
    if (p < B_ROWS) {
        int lab = get_label(sl, p);
        d_labS[p] = lab;
        float v = d_sscale[lab];
        #pragma unroll
        for (int c = 0; c < 32; c++) w[c] = (c == lab) ? v : 0.f;
    } else {
        int i = p - B_ROWS;
        const float* row = tl + (size_t)i * NCLS;
        #pragma unroll
        for (int c = 0; c < NCLS; c++) w[c] = -row[c] * d_tscale[c];
        w[31] = 0.f;
    }
}

// ---------------------------------------------------------------------------
// main tile kernel.
// Dynamic SMEM 65536 B: 4 stages x {Ah, Bh} x (128 rows x 64 B).
// Swizzle within 64B row: 16B chunk c (0..3) stored at c ^ ((row>>1)&3).
// Epilogue overlays stage memory after all cp.async groups drained.
// ---------------------------------------------------------------------------
#define SM_TOTAL (NSTAGE * STAGE_BYTES)
#define EP_SQA  0
#define EP_SQB  512
#define EP_LABA 1024
#define EP_LABB 1536
#define EP_SVA  2048
#define EP_SVB  2560
#define EP_WA   3072      // [128][32] f32, 16 KB
#define EP_WBT  19456     // [32][132] f32, 16.9 KB
#define EP_RED  36352

__global__ __launch_bounds__(256, 2)
void k_main() {
    extern __shared__ char smem[];
    uint32_t sb = smem_u32(smem);
    int tid = threadIdx.x, wid = tid >> 5, lane = tid & 31;
    int g = lane >> 2, t4 = lane & 3;
    int warp_m = wid & 3, warp_n = wid >> 2;

    // decode upper-triangular tile pair (I <= J)
    int t = blockIdx.x;
    int I = 0;
    while ((I + 1) * NT - ((I + 1) * I) / 2 <= t) I++;
    int J = I + (t - (I * NT - (I * (I - 1)) / 2));
    int rowA = I * BM, rowB = J * BM;

    // ldmatrix per-lane row mapping (x4: mats 0..3 from lane groups of 8)
    int a_rl  = (lane & 7) + ((lane >> 3) & 1) * 8;   // A local row 0..15
    int a_blk = lane >> 4;                            // A k-16B-block 0/1
    int b_nl  = (lane & 7) + ((lane >> 4) << 3);      // B local n 0..15
    int b_blk = (lane >> 3) & 1;

    uint32_t arow_off[2], arsw[2];
    #pragma unroll
    for (int mt = 0; mt < 2; mt++) {
        int r = warp_m * 32 + mt * 16 + a_rl;
        arow_off[mt] = (uint32_t)r * 64;
        arsw[mt] = (uint32_t)((r >> 1) & 3);
    }
    uint32_t brow_off[4], brsw[4];
    #pragma unroll
    for (int ng = 0; ng < 4; ng++) {
        int r = warp_n * 64 + ng * 16 + b_nl;
        brow_off[ng] = (uint32_t)r * 64;
        brsw[ng] = (uint32_t)((r >> 1) & 3);
    }

    float acc[2][8][4];
    #pragma unroll
    for (int mt = 0; mt < 2; mt++)
        #pragma unroll
        for (int nt = 0; nt < 8; nt++)
            #pragma unroll
            for (int e = 0; e < 4; e++) acc[mt][nt][e] = 0.f;

    // --- cp.async chunk loader: 4 x 16B per thread per chunk (16 KB) ---
    auto issue = [&](int ch, int buf) {
        int k0 = ch * KC;
        #pragma unroll
        for (int i = 0; i < 4; i++) {
            int q = i * 256 + tid;
            int tile = q >> 9;            // 0:Ah 1:Bh (512 ops each)
            int idx = q & 511;
            int row = idx >> 2;
            int c   = idx & 3;
            int rb = (tile == 0) ? rowA : rowB;
            const __half* src = d_Xh + (size_t)(rb + row) * D_DIM + k0 + c * 8;
            uint32_t dst = sb + (uint32_t)buf * STAGE_BYTES + (uint32_t)tile * TILE_BYTES
                         + (uint32_t)row * 64 + (uint32_t)((c ^ ((row >> 1) & 3)) << 4);
            CP_ASYNC16(dst, src);
        }
        CP_COMMIT();
    };

    issue(0, 0);
    issue(1, 1);
    issue(2, 2);
    for (int ch = 0; ch < NCHUNK; ch++) {
        int buf = ch % NSTAGE;
        if (ch + NSTAGE - 1 < NCHUNK) issue(ch + NSTAGE - 1, (ch + NSTAGE - 1) % NSTAGE);
        if (ch < NCHUNK - 3) CP_WAIT(3);
        else if (ch == NCHUNK - 3) CP_WAIT(2);
        else if (ch == NCHUNK - 2) CP_WAIT(1);
        else CP_WAIT(0);
        __syncthreads();

        uint32_t bufb = sb + (uint32_t)buf * STAGE_BYTES;
        #pragma unroll
        for (int ks = 0; ks < 2; ks++) {
            uint32_t ah[2][4], bb[4][4];
            #pragma unroll
            for (int mt = 0; mt < 2; mt++) {
                uint32_t ca = (((uint32_t)(ks * 2 + a_blk)) ^ arsw[mt]) << 4;
                LDSM4(ah[mt], bufb + arow_off[mt] + ca);
            }
            #pragma unroll
            for (int ng = 0; ng < 4; ng++) {
                uint32_t cb = (((uint32_t)(ks * 2 + b_blk)) ^ brsw[ng]) << 4;
                LDSM4(bb[ng], bufb + TILE_BYTES + brow_off[ng] + cb);
            }
            #pragma unroll
            for (int mt = 0; mt < 2; mt++)
                #pragma unroll
                for (int nt = 0; nt < 8; nt++)
                    mma_f16(acc[mt][nt], ah[mt], &bb[nt >> 1][(nt & 1) * 2]);
        }
        __syncthreads();
    }

    // ---- stage epilogue operands (overlays stages; all groups drained) ----
    bool srcA = (I < NSRCT), srcB = (J < NSRCT);
    float* SQA  = (float*)(smem + EP_SQA);
    float* SQB  = (float*)(smem + EP_SQB);
    int*   LABA = (int*)  (smem + EP_LABA);
    int*   LABB = (int*)  (smem + EP_LABB);
    float* SVA  = (float*)(smem + EP_SVA);
    float* SVB  = (float*)(smem + EP_SVB);
    float* WA   = (float*)(smem + EP_WA);
    float* WBT  = (float*)(smem + EP_WBT);
    float* RED  = (float*)(smem + EP_RED);

    if (tid < 128) { SQA[tid] = d_sq[rowA + tid]; SQB[tid] = d_sq[rowB + tid]; }
    if (srcA) {
        if (tid < 128) {
            int l = d_labS[rowA + tid];
            LABA[tid] = l; SVA[tid] = d_sscale[l];
        }
    } else {
        for (int m = tid * 4; m < BM * 32; m += 1024)
            *(float4*)&WA[m] = *(const float4*)&d_W[(size_t)rowA * 32 + m];
    }
    if (srcB) {
        if (tid < 128) {
            int l = d_labS[rowB + tid];
            LABB[tid] = l; SVB[tid] = d_sscale[l];
        }
    } else {
        for (int gq = tid; gq < BM * 32; gq += 256) {
            int j = gq >> 5, cc = gq & 31;
            WBT[cc * 132 + j] = d_W[(size_t)(rowB + j) * 32 + cc];
        }
    }
    __syncthreads();

    // ---- exp chain ----
    int rl[4], cl[16];
    float sqa4[4], sqb16[16];
    #pragma unroll
    for (int mt = 0; mt < 2; mt++)
        #pragma unroll
        for (int h = 0; h < 2; h++) {
            int r = warp_m * 32 + mt * 16 + h * 8 + g;
            rl[mt * 2 + h] = r; sqa4[mt * 2 + h] = SQA[r];
        }
    #pragma unroll
    for (int nt = 0; nt < 8; nt++)
        #pragma unroll
        for (int w = 0; w < 2; w++) {
            int c = warp_n * 64 + nt * 8 + 2 * t4 + w;
            cl[nt * 2 + w] = c; sqb16[nt * 2 + w] = SQB[c];
        }
    float cz = d_cz;
    float Kr[4][16];
    #pragma unroll
    for (int mt = 0; mt < 2; mt++)
        #pragma unroll
        for (int nt = 0; nt < 8; nt++)
            #pragma unroll
            for (int e = 0; e < 4; e++) {
                int r = mt * 2 + (e >> 1), c = nt * 2 + (e & 1);
                float l2 = fmaxf(sqa4[r] + sqb16[c] - 2.f * acc[mt][nt][e], 0.f);
                float z  = exp2f(l2 * cz);
                float z2 = z * z, z4 = z2 * z2, z8 = z4 * z4, z16 = z8 * z8;
                Kr[r][c] = ((z + z2) + (z4 + z8)) + z16;
            }

    // ---- weight contraction ----
    float lsum = 0.f;
    if (srcA) {
        int la[4]; float sa[4];
        #pragma unroll
        for (int r = 0; r < 4; r++) { la[r] = LABA[rl[r]]; sa[r] = SVA[rl[r]]; }
        if (srcB) {
            int lb[16]; float svb[16];
            #pragma unroll
            for (int j = 0; j < 16; j++) { lb[j] = LABB[cl[j]]; svb[j] = SVB[cl[j]]; }
            #pragma unroll
            for (int r = 0; r < 4; r++) {
                float s = 0.f;
                #pragma unroll
                for (int j = 0; j < 16; j++) {
                    float w = (lb[j] == la[r]) ? svb[j] : 0.f;
                    s = fmaf(w, Kr[r][j], s);
                }
                lsum = fmaf(sa[r], s, lsum);
            }
        } else {
            #pragma unroll
            for (int r = 0; r < 4; r++) {
                const float* wr = &WBT[la[r] * 132];
                float s = 0.f;
                #pragma unroll
                for (int j = 0; j < 16; j++)
                    s = fmaf(wr[cl[j]], Kr[r][j], s);
                lsum = fmaf(sa[r], s, lsum);
            }
        }
    } else {            // tt: both target
        for (int c = 0; c < NCLS; c++) {
            float wbv[16];
            #pragma unroll
            for (int j = 0; j < 16; j++) wbv[j] = WBT[c * 132 + cl[j]];
            #pragma unroll
            for (int r = 0; r < 4; r++) {
                float s = 0.f;
                #pragma unroll
                for (int j = 0; j < 16; j++) s = fmaf(wbv[j], Kr[r][j], s);
                lsum = fmaf(WA[rl[r] * 32 + c], s, lsum);
            }
        }
    }
    if (I != J) lsum *= 2.f;

    // ---- block reduction ----
    __syncthreads();
    RED[tid] = lsum;
    __syncthreads();
    for (int st = 128; st > 0; st >>= 1) {
        if (tid < st) RED[tid] += RED[tid + st];
        __syncthreads();
    }
    if (tid == 0) d_partial[blockIdx.x] = RED[0];
}

__global__ void k_reduce(float* out) {
    __shared__ float red[256];
    int tid = threadIdx.x;
    float s = 0.f;
    for (int i = tid; i < NPAIR; i += 256) s += d_partial[i];
    red[tid] = s;
    __syncthreads();
    for (int st = 128; st > 0; st >>= 1) {
        if (tid < st) red[tid] += red[tid + st];
        __syncthreads();
    }
    if (tid == 0) out[0] = red[0] * d_inv_nidx;
}

extern "C" void kernel_launch(void* const* d_in, const int* in_sizes, int n_in,
                              void* d_out, int out_size) {
    const float* src = (const float*)d_in[0];
    const float* tgt = (const float*)d_in[1];
    const void*  sl  = d_in[2];
    const float* tl  = (const float*)d_in[3];
    float* out = (float*)d_out;

    cudaFuncSetAttribute(k_main, cudaFuncAttributeMaxDynamicSharedMemorySize, SM_TOTAL);

    k_detect  <<<1,    256>>>(sl);
    k_zero    <<<1,    256>>>();
    k_stats   <<<16,   256>>>(sl, tl);
    k_prep    <<<1024, 256>>>(src, tgt);
    k_finalize<<<1,    256>>>();
    k_weights <<<32,   256>>>(sl, tl);
    k_main    <<<NPAIR, 256, SM_TOTAL>>>();
    k_reduce  <<<1,    256>>>(out);
}

// round 16
// speedup vs baseline: 1.5548x; 1.5548x over previous
#include <cuda_runtime.h>
#include <cuda_bf16.h>
#include <cstdint>

// ---------------------------------------------------------------------------
// LMMD loss — HMMA bf16 SINGLE-term Gram mainloop + fused epilogue.
//   bw closed form: sum(l2) = 2n*sum(||x||^2) - 2*||sum x||^2  (fp32/double)
//   K(l2) = z + z^2 + z^4 + z^8 + z^16, z = exp(-l2/(16*bw))
//   loss = (1/n_idx) * sum_pq (u_p.u_q) K_pq, u = +s_vec / -t_vec rows.
//   Upper-triangular 128x128 tiles only (x2 off-diagonal).
//   g ~= bf16(x) . bf16(y)  (fp32 accum; sq-norms exact fp32)
// R16: cross-round evidence => bf16 HMMA rt~25cyc/SMSP, f16 HMMA rt~75 (3x
//      slower legacy path). Single-term bf16 = R15's MMA count at R13's rate.
//      KC=64 (fewer barriers), 3-stage pipe, 96KB SMEM, 2 CTAs/SM.
// ---------------------------------------------------------------------------

#define B_ROWS 4096
#define D_DIM  256
#define NCLS   31
#define NTOT   8192
#define BM     128
#define KC     64              // K per chunk = 128B bf16 rows
#define NCHUNK 4
#define NSTAGE 3
#define NT     64
#define NPAIR  2080
#define NSRCT  32              // tiles 0..31 hold source rows

#define TILE_BYTES  16384      // 128 rows x 128 B
#define STAGE_BYTES 32768      // 2 tiles (Ah, Bh)

// ---- device scratch ----
__device__ __align__(16) __nv_bfloat16 d_Xh[NTOT * D_DIM];
__device__ __align__(16) float d_W[NTOT * 32];
__device__ int   d_labS[B_ROWS];
__device__ float d_sq[NTOT];
__device__ float d_colsum[D_DIM];
__device__ float d_scnt[NCLS];
__device__ float d_tcnt[NCLS];
__device__ float d_targc[NCLS];
__device__ float d_sscale[NCLS];
__device__ float d_tscale[NCLS];
__device__ float d_cz;
__device__ float d_inv_nidx;
__device__ float d_partial[NPAIR];
__device__ int   d_lab64;

// ---- helpers ----
__device__ __forceinline__ uint32_t smem_u32(const void* p) {
    uint32_t a;
    asm("{ .reg .u64 t; cvta.to.shared.u64 t, %1; cvt.u32.u64 %0, t; }" : "=r"(a) : "l"(p));
    return a;
}
#define CP_ASYNC16(dst, src) \
    asm volatile("cp.async.cg.shared.global [%0], [%1], 16;" :: "r"(dst), "l"(src))
#define CP_COMMIT() asm volatile("cp.async.commit_group;" ::: "memory")
#define CP_WAIT(n)  asm volatile("cp.async.wait_group %0;" :: "n"(n) : "memory")

#define LDSM4(r, a) \
    asm volatile("ldmatrix.sync.aligned.m8n8.x4.shared.b16 {%0,%1,%2,%3}, [%4];" \
        : "=r"((r)[0]), "=r"((r)[1]), "=r"((r)[2]), "=r"((r)[3]) : "r"(a))

__device__ __forceinline__ void mma_bf16(float* c, const uint32_t* a, const uint32_t* b) {
    asm volatile(
        "mma.sync.aligned.m16n8k16.row.col.f32.bf16.bf16.f32 "
        "{%0,%1,%2,%3}, {%4,%5,%6,%7}, {%8,%9}, {%0,%1,%2,%3};"
        : "+f"(c[0]), "+f"(c[1]), "+f"(c[2]), "+f"(c[3])
        : "r"(a[0]), "r"(a[1]), "r"(a[2]), "r"(a[3]), "r"(b[0]), "r"(b[1]));
}

__device__ __forceinline__ const float* row_ptr(const float* s, const float* t, int p) {
    return (p < B_ROWS) ? (s + (size_t)p * D_DIM) : (t + (size_t)(p - B_ROWS) * D_DIM);
}
__device__ __forceinline__ int get_label(const void* sl, int i) {
    if (d_lab64) return (int)((const long long*)sl)[i];
    return ((const int*)sl)[i];
}

// ---------------------------------------------------------------------------
// small kernels
// ---------------------------------------------------------------------------
__global__ void k_detect(const void* sl) {
    __shared__ int any;
    if (threadIdx.x == 0) any = 0;
    __syncthreads();
    const int* a = (const int*)sl;
    int local = 0;
    for (int i = threadIdx.x; i < 2048; i += blockDim.x)
        if (a[2 * i + 1] != 0) local = 1;
    if (local) atomicOr(&any, 1);
    __syncthreads();
    if (threadIdx.x == 0) d_lab64 = any ? 0 : 1;
}

__global__ void k_zero() {
    int t = threadIdx.x;
    if (t < NCLS) { d_scnt[t] = 0.f; d_tcnt[t] = 0.f; d_targc[t] = 0.f; }
    if (t < D_DIM) d_colsum[t] = 0.f;
}

__global__ void k_stats(const void* sl, const float* __restrict__ tl) {
    __shared__ float ssh[NCLS], tsh[NCLS], ash[NCLS];
    int tid = threadIdx.x;
    if (tid < NCLS) { ssh[tid] = 0.f; tsh[tid] = 0.f; ash[tid] = 0.f; }
    __syncthreads();
    int i = blockIdx.x * 256 + tid;
    int lab = get_label(sl, i);
    atomicAdd(&ssh[lab], 1.f);
    const float* row = tl + (size_t)i * NCLS;
    float best = row[0];
    int arg = 0;
    atomicAdd(&tsh[0], best);
    #pragma unroll
    for (int c = 1; c < NCLS; c++) {
        float v = row[c];
        atomicAdd(&tsh[c], v);
        if (v > best) { best = v; arg = c; }
    }
    atomicAdd(&ash[arg], 1.f);
    __syncthreads();
    if (tid < NCLS) {
        atomicAdd(&d_scnt[tid],  ssh[tid]);
        atomicAdd(&d_tcnt[tid],  tsh[tid]);
        atomicAdd(&d_targc[tid], ash[tid]);
    }
}

// fused: column sums + row sq-norms + bf16 conversion.  grid 1024 x 256
__global__ void k_prep(const float* __restrict__ src, const float* __restrict__ tgt) {
    __shared__ float cs[256];
    int tid = threadIdx.x;
    cs[tid] = 0.f;
    __syncthreads();
    int w = tid >> 5, lane = tid & 31;
    int row = blockIdx.x * 8 + w;
    const float* p = row_ptr(src, tgt, row) + lane * 8;
    float4 v0 = *(const float4*)p;
    float4 v1 = *(const float4*)(p + 4);
    float xs[8] = {v0.x, v0.y, v0.z, v0.w, v1.x, v1.y, v1.z, v1.w};

    float s = 0.f;
    #pragma unroll
    for (int e = 0; e < 8; e++) s = fmaf(xs[e], xs[e], s);
    #pragma unroll
    for (int off = 16; off > 0; off >>= 1) s += __shfl_xor_sync(0xffffffffu, s, off);
    if (lane == 0) d_sq[row] = s;

    int cb = lane * 8;
    #pragma unroll
    for (int e = 0; e < 8; e++) atomicAdd(&cs[cb + e], xs[e]);

    uint32_t ph[4];
    #pragma unroll
    for (int e = 0; e < 4; e++) {
        __nv_bfloat16 h0 = __float2bfloat16_rn(xs[2 * e]);
        __nv_bfloat16 h1 = __float2bfloat16_rn(xs[2 * e + 1]);
        ph[e] = (uint32_t)__bfloat16_as_ushort(h0) | ((uint32_t)__bfloat16_as_ushort(h1) << 16);
    }
    size_t o = (size_t)row * D_DIM + lane * 8;
    *(uint4*)(d_Xh + o) = make_uint4(ph[0], ph[1], ph[2], ph[3]);

    __syncthreads();
    atomicAdd(&d_colsum[tid], cs[tid]);
}

__global__ void k_finalize() {
    __shared__ double dred[256];
    int tid = threadIdx.x;
    if (tid == 0) {
        float nidx = 0.f;
        for (int c = 0; c < NCLS; c++) {
            float m = (d_scnt[c] > 0.f && d_targc[c] > 0.f) ? 1.f : 0.f;
            nidx += m;
            float sden = (d_scnt[c] == 0.f) ? 100.f : d_scnt[c];
            float tden = (d_tcnt[c] == 0.f) ? 100.f : d_tcnt[c];
            d_sscale[c] = m / sden;
            d_tscale[c] = m / tden;
        }
        if (nidx < 1.f) nidx = 1.f;
        d_inv_nidx = 1.f / nidx;
    }
    double s = 0.0;
    for (int i = tid; i < NTOT; i += 256)
        s += (double)d_sq[i] * (2.0 * (double)NTOT);
    for (int i = tid; i < D_DIM; i += 256) {
        double v = (double)d_colsum[i];
        s -= 2.0 * v * v;
    }
    dred[tid] = s;
    __syncthreads();
    for (int st = 128; st > 0; st >>= 1) {
        if (tid < st) dred[tid] += dred[tid + st];
        __syncthreads();
    }
    if (tid == 0) {
        float bw = (float)(dred[0] / (8192.0 * 8192.0 - 8192.0));
        bw = fmaxf(bw, 1e-6f) * 0.25f;
        d_cz = -1.4426950408889634f / (bw * 16.f);
    }
}

__global__ void k_weights(const void* sl, const float* __restrict__ tl) {
    int p = blockIdx.x * 256 + threadIdx.x;
    float* w = d_W + (size_t)p * 32;
    if (p < B_ROWS) {
        int lab = get_label(sl, p);
        d_labS[p] = lab;
        float v = d_sscale[lab];
        #pragma unroll
        for (int c = 0; c < 32; c++) w[c] = (c == lab) ? v : 0.f;
    } else {
        int i = p - B_ROWS;
        const float* row = tl + (size_t)i * NCLS;
        #pragma unroll
        for (int c = 0; c < NCLS; c++) w[c] = -row[c] * d_tscale[c];
        w[31] = 0.f;
    }
}

// ---------------------------------------------------------------------------
// main tile kernel.
// Dynamic SMEM 98304 B: 3 stages x {Ah, Bh} x (128 rows x 128 B).
// Swizzle within 128B row: 16B chunk c (0..7) stored at c ^ (row&7)
//   (R11-proven: 8 rows of a ldmatrix matrix hit 8 distinct 16B slots).
// Epilogue overlays stage memory after all cp.async groups drained.
// ---------------------------------------------------------------------------
#define SM_TOTAL (NSTAGE * STAGE_BYTES)
#define EP_SQA  0
#define EP_SQB  512
#define EP_LABA 1024
#define EP_LABB 1536
#define EP_SVA  2048
#define EP_SVB  2560
#define EP_WA   3072      // [128][32] f32, 16 KB
#define EP_WBT  19456     // [32][132] f32, 16.9 KB
#define EP_RED  36352

__global__ __launch_bounds__(256, 2)
void k_main() {
    extern __shared__ char smem[];
    uint32_t sb = smem_u32(smem);
    int tid = threadIdx.x, wid = tid >> 5, lane = tid & 31;
    int g = lane >> 2, t4 = lane & 3;
    int warp_m = wid & 3, warp_n = wid >> 2;

    // decode upper-triangular tile pair (I <= J)
    int t = blockIdx.x;
    int I = 0;
    while ((I + 1) * NT - ((I + 1) * I) / 2 <= t) I++;
    int J = I + (t - (I * NT - (I * (I - 1)) / 2));
    int rowA = I * BM, rowB = J * BM;

    // ldmatrix per-lane row mapping (x4: mats 0..3 from lane groups of 8)
    int a_rl  = (lane & 7) + ((lane >> 3) & 1) * 8;   // A local row 0..15
    int a_blk = lane >> 4;                            // A k-16B-block 0/1
    int b_nl  = (lane & 7) + ((lane >> 4) << 3);      // B local n 0..15
    int b_blk = (lane >> 3) & 1;

    uint32_t arow_off[2], arsw[2];
    #pragma unroll
    for (int mt = 0; mt < 2; mt++) {
        int r = warp_m * 32 + mt * 16 + a_rl;
        arow_off[mt] = (uint32_t)r * 128;
        arsw[mt] = (uint32_t)(r & 7);
    }
    uint32_t brow_off[4], brsw[4];
    #pragma unroll
    for (int ng = 0; ng < 4; ng++) {
        int r = warp_n * 64 + ng * 16 + b_nl;
        brow_off[ng] = (uint32_t)r * 128;
        brsw[ng] = (uint32_t)(r & 7);
    }

    float acc[2][8][4];
    #pragma unroll
    for (int mt = 0; mt < 2; mt++)
        #pragma unroll
        for (int nt = 0; nt < 8; nt++)
            #pragma unroll
            for (int e = 0; e < 4; e++) acc[mt][nt][e] = 0.f;

    // --- cp.async chunk loader: 8 x 16B per thread per chunk (32 KB) ---
    auto issue = [&](int ch, int buf) {
        int k0 = ch * KC;
        #pragma unroll
        for (int i = 0; i < 8; i++) {
            int q = i * 256 + tid;
            int tile = q >> 10;           // 0:Ah 1:Bh (1024 ops each)
            int idx = q & 1023;
            int row = idx >> 3;
            int c   = idx & 7;
            int rb = (tile == 0) ? rowA : rowB;
            const __nv_bfloat16* src = d_Xh + (size_t)(rb + row) * D_DIM + k0 + c * 8;
            uint32_t dst = sb + (uint32_t)buf * STAGE_BYTES + (uint32_t)tile * TILE_BYTES
                         + (uint32_t)row * 128 + (uint32_t)((c ^ (row & 7)) << 4);
            CP_ASYNC16(dst, src);
        }
        CP_COMMIT();
    };

    issue(0, 0);
    issue(1, 1);
    for (int ch = 0; ch < NCHUNK; ch++) {
        int buf = ch % NSTAGE;
        if (ch + 2 < NCHUNK) issue(ch + 2, (ch + 2) % NSTAGE);
        if (ch < NCHUNK - 2) CP_WAIT(2);
        else if (ch == NCHUNK - 2) CP_WAIT(1);
        else CP_WAIT(0);
        __syncthreads();

        uint32_t bufb = sb + (uint32_t)buf * STAGE_BYTES;
        #pragma unroll
        for (int ks = 0; ks < 4; ks++) {
            uint32_t ah[2][4], bb[4][4];
            #pragma unroll
            for (int mt = 0; mt < 2; mt++) {
                uint32_t ca = (((uint32_t)(ks * 2 + a_blk)) ^ arsw[mt]) << 4;
                LDSM4(ah[mt], bufb + arow_off[mt] + ca);
            }
            #pragma unroll
            for (int ng = 0; ng < 4; ng++) {
                uint32_t cb = (((uint32_t)(ks * 2 + b_blk)) ^ brsw[ng]) << 4;
                LDSM4(bb[ng], bufb + TILE_BYTES + brow_off[ng] + cb);
            }
            #pragma unroll
            for (int mt = 0; mt < 2; mt++)
                #pragma unroll
                for (int nt = 0; nt < 8; nt++)
                    mma_bf16(acc[mt][nt], ah[mt], &bb[nt >> 1][(nt & 1) * 2]);
        }
        __syncthreads();
    }

    // ---- stage epilogue operands (overlays stages; all groups drained) ----
    bool srcA = (I < NSRCT), srcB = (J < NSRCT);
    float* SQA  = (float*)(smem + EP_SQA);
    float* SQB  = (float*)(smem + EP_SQB);
    int*   LABA = (int*)  (smem + EP_LABA);
    int*   LABB = (int*)  (smem + EP_LABB);
    float* SVA  = (float*)(smem + EP_SVA);
    float* SVB  = (float*)(smem + EP_SVB);
    float* WA   = (float*)(smem + EP_WA);
    float* WBT  = (float*)(smem + EP_WBT);
    float* RED  = (float*)(smem + EP_RED);

    if (tid < 128) { SQA[tid] = d_sq[rowA + tid]; SQB[tid] = d_sq[rowB + tid]; }
    if (srcA) {
        if (tid < 128) {
            int l = d_labS[rowA + tid];
            LABA[tid] = l; SVA[tid] = d_sscale[l];
        }
    } else {
        for (int m = tid * 4; m < BM * 32; m += 1024)
            *(float4*)&WA[m] = *(const float4*)&d_W[(size_t)rowA * 32 + m];
    }
    if (srcB) {
        if (tid < 128) {
            int l = d_labS[rowB + tid];
            LABB[tid] = l; SVB[tid] = d_sscale[l];
        }
    } else {
        for (int gq = tid; gq < BM * 32; gq += 256) {
            int j = gq >> 5, cc = gq & 31;
            WBT[cc * 132 + j] = d_W[(size_t)(rowB + j) * 32 + cc];
        }
    }
    __syncthreads();

    // ---- exp chain ----
    int rl[4], cl[16];
    float sqa4[4], sqb16[16];
    #pragma unroll
    for (int mt = 0; mt < 2; mt++)
        #pragma unroll
        for (int h = 0; h < 2; h++) {
            int r = warp_m * 32 + mt * 16 + h * 8 + g;
            rl[mt * 2 + h] = r; sqa4[mt * 2 + h] = SQA[r];
        }
    #pragma unroll
    for (int nt = 0; nt < 8; nt++)
        #pragma unroll
        for (int w = 0; w < 2; w++) {
            int c = warp_n * 64 + nt * 8 + 2 * t4 + w;
            cl[nt * 2 + w] = c; sqb16[nt * 2 + w] = SQB[c];
        }
    float cz = d_cz;
    float Kr[4][16];
    #pragma unroll
    for (int mt = 0; mt < 2; mt++)
        #pragma unroll
        for (int nt = 0; nt < 8; nt++)
            #pragma unroll
            for (int e = 0; e < 4; e++) {
                int r = mt * 2 + (e >> 1), c = nt * 2 + (e & 1);
                float l2 = fmaxf(sqa4[r] + sqb16[c] - 2.f * acc[mt][nt][e], 0.f);
                float z  = exp2f(l2 * cz);
                float z2 = z * z, z4 = z2 * z2, z8 = z4 * z4, z16 = z8 * z8;
                Kr[r][c] = ((z + z2) + (z4 + z8)) + z16;
            }

    // ---- weight contraction ----
    float lsum = 0.f;
    if (srcA) {
        int la[4]; float sa[4];
        #pragma unroll
        for (int r = 0; r < 4; r++) { la[r] = LABA[rl[r]]; sa[r] = SVA[rl[r]]; }
        if (srcB) {
            int lb[16]; float svb[16];
            #pragma unroll
            for (int j = 0; j < 16; j++) { lb[j] = LABB[cl[j]]; svb[j] = SVB[cl[j]]; }
            #pragma unroll
            for (int r = 0; r < 4; r++) {
                float s = 0.f;
                #pragma unroll
                for (int j = 0; j < 16; j++) {
                    float w = (lb[j] == la[r]) ? svb[j] : 0.f;
                    s = fmaf(w, Kr[r][j], s);
                }
                lsum = fmaf(sa[r], s, lsum);
            }
        } else {
            #pragma unroll
            for (int r = 0; r < 4; r++) {
                const float* wr = &WBT[la[r] * 132];
                float s = 0.f;
                #pragma unroll
                for (int j = 0; j < 16; j++)
                    s = fmaf(wr[cl[j]], Kr[r][j], s);
                lsum = fmaf(sa[r], s, lsum);
            }
        }
    } else {            // tt: both target
        for (int c = 0; c < NCLS; c++) {
            float wbv[16];
            #pragma unroll
            for (int j = 0; j < 16; j++) wbv[j] = WBT[c * 132 + cl[j]];
            #pragma unroll
            for (int r = 0; r < 4; r++) {
                float s = 0.f;
                #pragma unroll
                for (int j = 0; j < 16; j++) s = fmaf(wbv[j], Kr[r][j], s);
                lsum = fmaf(WA[rl[r] * 32 + c], s, lsum);
            }
        }
    }
    if (I != J) lsum *= 2.f;

    // ---- block reduction ----
    __syncthreads();
    RED[tid] = lsum;
    __syncthreads();
    for (int st = 128; st > 0; st >>= 1) {
        if (tid < st) RED[tid] += RED[tid + st];
        __syncthreads();
    }
    if (tid == 0) d_partial[blockIdx.x] = RED[0];
}

__global__ void k_reduce(float* out) {
    __shared__ float red[256];
    int tid = threadIdx.x;
    float s = 0.f;
    for (int i = tid; i < NPAIR; i += 256) s += d_partial[i];
    red[tid] = s;
    __syncthreads();
    for (int st = 128; st > 0; st >>= 1) {
        if (tid < st) red[tid] += red[tid + st];
        __syncthreads();
    }
    if (tid == 0) out[0] = red[0] * d_inv_nidx;
}

extern "C" void kernel_launch(void* const* d_in, const int* in_sizes, int n_in,
                              void* d_out, int out_size) {
    const float* src = (const float*)d_in[0];
    const float* tgt = (const float*)d_in[1];
    const void*  sl  = d_in[2];
    const float* tl  = (const float*)d_in[3];
    float* out = (float*)d_out;

    cudaFuncSetAttribute(k_main, cudaFuncAttributeMaxDynamicSharedMemorySize, SM_TOTAL);

    k_detect  <<<1,    256>>>(sl);
    k_zero    <<<1,    256>>>();
    k_stats   <<<16,   256>>>(sl, tl);
    k_prep    <<<1024, 256>>>(src, tgt);
    k_finalize<<<1,    256>>>();
    k_weights <<<32,   256>>>(sl, tl);
    k_main    <<<NPAIR, 256, SM_TOTAL>>>();
    k_reduce  <<<1,    256>>>(out);
}